// round 10
// baseline (speedup 1.0000x reference)
#include <cuda_runtime.h>
#include <cuda_fp16.h>
#include <mma.h>
#include <cstdint>

using namespace nvcuda;

namespace {
constexpr int B   = 4;
constexpr int T   = 2048;
constexpr int HID = 1024;
constexpr int NH  = 16;
constexpr int HS  = 64;
constexpr long long OUT_ELEMS = (long long)B * T * HID;
constexpr int QT  = T / 64;
constexpr int KT  = T / 64;
constexpr int KC  = 8;              // k-chunks in stage B
constexpr int KPC = KT / KC;        // 4 k-tiles per chunk
constexpr int HP  = 72;             // attention smem pitch (halves/floats)
constexpr long long PSLICE = (long long)B * T * HS;

// gemm tiling
constexpr int GP  = 40;             // As pitch (halves): 32 + 8
constexpr int GBP = 136;            // Bs pitch (halves): 128 + 8
constexpr int CPF = 136;            // Cs pitch (floats)
constexpr int BUF_BYTES = 128 * GP * 2 + 32 * GBP * 2;  // 18944
constexpr int NSTAGE = 3;                               // 3 * 18944 = 56832
constexpr int GEMM_SMEM = 128 * CPF * 4;                // 69632 (>= 3*BUF_BYTES)

// stage A smem: Qs 9216 | Kb 2x9216 | Ss 2x18432  = 64512
constexpr int ASA_SMEM = 9216 + 2 * 9216 + 2 * 18432;
}

// ---- scratch (static device globals) ----
__device__ __half g_xh[(size_t)B * T * HID];
__device__ __half g_Wqh[(size_t)HID * HID];
__device__ __half g_Wkh[(size_t)HID * HID];
__device__ __half g_Wvh[(size_t)HID * HS];
__device__ __half g_Woh[(size_t)HS * HID];
__device__ __half g_Q[(size_t)B * T * HID];      // pre-scaled by 0.125
__device__ __half g_K[(size_t)B * T * HID];
__device__ __half g_V[(size_t)B * T * HS];
__device__ float  g_wS[(size_t)B * NH * T];      // 1/(16*Z)
__device__ float  g_Opart[(size_t)KC * B * T * HS];
__device__ __half g_Ored[(size_t)B * T * HS];
__device__ __half g_E[(size_t)B * NH * T * T];   // exp(s-4)

// ---- cp.async helpers ----
__device__ __forceinline__ void cp_async16(unsigned int dst, const void* src, int src_bytes) {
    asm volatile("cp.async.ca.shared.global [%0], [%1], 16, %2;\n"
                 :: "r"(dst), "l"(src), "r"(src_bytes));
}
__device__ __forceinline__ void cp_commit() {
    asm volatile("cp.async.commit_group;\n" ::: "memory");
}
template<int N>
__device__ __forceinline__ void cp_wait() {
    asm volatile("cp.async.wait_group %0;\n" :: "n"(N) : "memory");
}
__device__ __forceinline__ unsigned int smem_addr(const void* p) {
    return (unsigned int)__cvta_generic_to_shared(p);
}

// ============================================================================
// Merged fp32 -> fp16 conversion for x, Wq, Wk, Wv, Wo (grid-stride, float4)
// ============================================================================
__global__ void conv_all(const float* __restrict__ x, const float* __restrict__ wq,
                         const float* __restrict__ wk, const float* __restrict__ wv,
                         const float* __restrict__ wo)
{
    constexpr int NX = (B * T * HID) / 4;
    constexpr int NW = (HID * HID) / 4;
    constexpr int NV = (HID * HS) / 4;
    constexpr int NO = (HS * HID) / 4;
    constexpr int TOT = NX + 2 * NW + NV + NO;

    for (int i = blockIdx.x * blockDim.x + threadIdx.x; i < TOT;
         i += gridDim.x * blockDim.x) {
        const float* src; __half* dst; int off;
        if (i < NX)                     { src = x;  dst = g_xh;  off = i; }
        else if (i < NX + NW)           { src = wq; dst = g_Wqh; off = i - NX; }
        else if (i < NX + 2 * NW)       { src = wk; dst = g_Wkh; off = i - NX - NW; }
        else if (i < NX + 2 * NW + NV)  { src = wv; dst = g_Wvh; off = i - NX - 2 * NW; }
        else                            { src = wo; dst = g_Woh; off = i - NX - 2 * NW - NV; }
        float4 v = ((const float4*)src)[off];
        __half2 h0 = __floats2half2_rn(v.x, v.y);
        __half2 h1 = __floats2half2_rn(v.z, v.w);
        uint2 u;
        u.x = *(unsigned int*)&h0;
        u.y = *(unsigned int*)&h1;
        ((uint2*)dst)[off] = u;
    }
}

// ============================================================================
// Reduce KC Opart fp32 slices -> fp16 g_Ored
// ============================================================================
__global__ void reduceN_f16(const float* __restrict__ A)
{
    int i = blockIdx.x * blockDim.x + threadIdx.x;   // float4 index
    constexpr int N4 = (int)(PSLICE / 4);
    if (i < N4) {
        float4 v = ((const float4*)A)[i];
#pragma unroll
        for (int p = 1; p < KC; p++) {
            float4 w = ((const float4*)(A + p * PSLICE))[i];
            v.x += w.x; v.y += w.y; v.z += w.z; v.w += w.w;
        }
        __half2 h0 = __floats2half2_rn(v.x, v.y);
        __half2 h1 = __floats2half2_rn(v.z, v.w);
        uint2 u;
        u.x = *(unsigned int*)&h0;
        u.y = *(unsigned int*)&h1;
        ((uint2*)g_Ored)[i] = u;
    }
}

// ============================================================================
// fp16 GEMM v3: C[M,N] = A[M,K] @ W[K,N] (+bias)*oscale.
// BM=128, BN=128, BK=32, cp.async 3-stage pipeline. 256 thr, 8 warps (4x2),
// warp tile 32x64. Output fp16 (Ch) or fp32 (Cf). N<128 guarded.
// ============================================================================
__global__ __launch_bounds__(256, 2) void gemm_f16_v2(
    const __half* __restrict__ A, const __half* __restrict__ W,
    const float* __restrict__ bias, __half* __restrict__ Ch,
    float* __restrict__ Cf, float oscale, int M, int N, int K)
{
    extern __shared__ char dsm[];

    const int tid = threadIdx.x;
    const int wid = tid >> 5;
    const int wq = wid >> 1;
    const int wn = wid & 1;
    const long long row0 = (long long)blockIdx.y * 128;
    const int n0 = blockIdx.x * 128;

    wmma::fragment<wmma::accumulator, 16, 16, 16, float> c[2][4];
#pragma unroll
    for (int i = 0; i < 2; i++)
#pragma unroll
        for (int j = 0; j < 4; j++) wmma::fill_fragment(c[i][j], 0.f);

    const int nkb = K / 32;

    auto issue = [&](int kb) {
        const int k0 = kb * 32;
        char* base = dsm + (kb % NSTAGE) * BUF_BYTES;
        __half* As = (__half*)base;
        __half* Bs = (__half*)(base + 128 * GP * 2);
#pragma unroll
        for (int i = 0; i < 2; i++) {
            int ci = tid + i * 256;
            int r = ci >> 2, off = (ci & 3) * 8;
            cp_async16(smem_addr(&As[r * GP + off]),
                       &A[(row0 + r) * K + k0 + off], 16);
        }
#pragma unroll
        for (int i = 0; i < 2; i++) {
            int ci = tid + i * 256;
            int r = ci >> 4, off = (ci & 15) * 8;
            bool ok = (n0 + off) < N;
            const void* src = ok ? (const void*)&W[(long long)(k0 + r) * N + n0 + off]
                                 : (const void*)W;
            cp_async16(smem_addr(&Bs[r * GBP + off]), src, ok ? 16 : 0);
        }
        cp_commit();
    };

    issue(0);
    if (nkb > 1) issue(1);

    for (int kb = 0; kb < nkb; kb++) {
        if (kb + 2 < nkb) {
            issue(kb + 2);
            cp_wait<2>();
        } else if (kb + 1 < nkb) {
            cp_wait<1>();
        } else {
            cp_wait<0>();
        }
        __syncthreads();

        char* base = dsm + (kb % NSTAGE) * BUF_BYTES;
        __half* As = (__half*)base;
        __half* Bs = (__half*)(base + 128 * GP * 2);

#pragma unroll
        for (int ks = 0; ks < 2; ks++) {
            wmma::fragment<wmma::matrix_a, 16, 16, 16, __half, wmma::row_major> a0, a1;
            wmma::load_matrix_sync(a0, &As[(wq * 32) * GP + ks * 16], GP);
            wmma::load_matrix_sync(a1, &As[(wq * 32 + 16) * GP + ks * 16], GP);
#pragma unroll
            for (int n = 0; n < 4; n++) {
                wmma::fragment<wmma::matrix_b, 16, 16, 16, __half, wmma::row_major> bf;
                wmma::load_matrix_sync(bf, &Bs[(ks * 16) * GBP + wn * 64 + n * 16], GBP);
                wmma::mma_sync(c[0][n], a0, bf, c[0][n]);
                wmma::mma_sync(c[1][n], a1, bf, c[1][n]);
            }
        }
        __syncthreads();
    }

    // epilogue through smem
    float* Cs = (float*)dsm;                 // [128][CPF]
#pragma unroll
    for (int i = 0; i < 2; i++)
#pragma unroll
        for (int j = 0; j < 4; j++)
            wmma::store_matrix_sync(&Cs[(wq * 32 + i * 16) * CPF + wn * 64 + j * 16],
                                    c[i][j], CPF, wmma::mem_row_major);
    __syncthreads();

#pragma unroll
    for (int i = 0; i < 16; i++) {
        int idx = tid + i * 256;
        int r = idx >> 5, c4 = (idx & 31) * 4;
        int col = n0 + c4;
        if (col < N) {
            float4 v = *(float4*)&Cs[r * CPF + c4];
            v.x = (v.x + bias[col])     * oscale;
            v.y = (v.y + bias[col + 1]) * oscale;
            v.z = (v.z + bias[col + 2]) * oscale;
            v.w = (v.w + bias[col + 3]) * oscale;
            if (Cf) {
                *(float4*)&Cf[(row0 + r) * N + col] = v;
            } else {
                __half2 h0 = __floats2half2_rn(v.x, v.y);
                __half2 h1 = __floats2half2_rn(v.z, v.w);
                uint2 u;
                u.x = *(unsigned int*)&h0;
                u.y = *(unsigned int*)&h1;
                *(uint2*)&Ch[(row0 + r) * N + col] = u;
            }
        }
    }
}

// ============================================================================
// Stage A v3: per (qt, h, b) block, S = Q_h K_h^T over all kt,
// E = exp(s-4) -> g_E (fp16), row sums -> g_wS.
// 256 thr, 8 warps 2(row)x4(col), warp tile 32x16 (halves B-frag traffic).
// K and S double-buffered; ONE barrier per k-tile.
// Dynamic smem: Qs 9216 | Kb 2x9216 | Ss 2x18432 = 64512 B.
// ============================================================================
__global__ __launch_bounds__(256, 2) void attn_scores()
{
    extern __shared__ char smraw[];
    __half* Qs = (__half*)smraw;                    // [64][HP]
    __half* Kb = Qs + 64 * HP;                      // 2 x [64][HP]
    float*  Sb = (float*)(smraw + 9216 + 18432);    // 2 x [64][HP] fp32

    const int qt = blockIdx.x;
    const int h  = blockIdx.y;
    const int b  = blockIdx.z;
    const int tid = threadIdx.x;
    const int wid = tid >> 5;
    const int wr = wid >> 2;           // 0..1 : 32-row group
    const int wc = wid & 3;            // 0..3 : 16-col group
    const int r0   = tid >> 3;         // 0..31
    const int colg = (tid & 7) * 8;

    const long long qrow0 = (long long)b * T + qt * 64;
    const long long krow0 = (long long)b * T;
    const size_t eBase = ((size_t)((b * QT + qt) * NH) + h) * ((size_t)KT * 4096);

    // load Q tile (2 rows per thread), preload K kt=0
    *(uint4*)&Qs[r0 * HP + colg] =
        *(const uint4*)&g_Q[(qrow0 + r0) * HID + h * 64 + colg];
    *(uint4*)&Qs[(r0 + 32) * HP + colg] =
        *(const uint4*)&g_Q[(qrow0 + r0 + 32) * HID + h * 64 + colg];
    *(uint4*)&Kb[r0 * HP + colg] =
        *(const uint4*)&g_K[(krow0 + r0) * HID + h * 64 + colg];
    *(uint4*)&Kb[(r0 + 32) * HP + colg] =
        *(const uint4*)&g_K[(krow0 + r0 + 32) * HID + h * 64 + colg];
    __syncthreads();

    // cache Q fragments: warp rows wr*32 .. wr*32+31, all K=64
    wmma::fragment<wmma::matrix_a, 16, 16, 16, __half, wmma::row_major> af[2][4];
#pragma unroll
    for (int m = 0; m < 2; m++)
#pragma unroll
        for (int ks = 0; ks < 4; ks++)
            wmma::load_matrix_sync(af[m][ks],
                &Qs[(wr * 32 + m * 16) * HP + ks * 16], HP);

    float zacc0 = 0.f, zacc1 = 0.f;

    for (int kt = 0; kt < KT; kt++) {
        const int cur = kt & 1;
        uint4 kreg0, kreg1;
        const bool havenext = (kt + 1) < KT;
        if (havenext) {
            kreg0 = *(const uint4*)&g_K[(krow0 + (kt + 1) * 64 + r0) * HID + h * 64 + colg];
            kreg1 = *(const uint4*)&g_K[(krow0 + (kt + 1) * 64 + r0 + 32) * HID + h * 64 + colg];
        }

        wmma::fragment<wmma::accumulator, 16, 16, 16, float> c[2];
        wmma::fill_fragment(c[0], 0.f);
        wmma::fill_fragment(c[1], 0.f);
        const __half* Kc = Kb + cur * (64 * HP);
#pragma unroll
        for (int ks = 0; ks < 4; ks++) {
            wmma::fragment<wmma::matrix_b, 16, 16, 16, __half, wmma::col_major> bf;
            wmma::load_matrix_sync(bf, &Kc[(wc * 16) * HP + ks * 16], HP);
            wmma::mma_sync(c[0], af[0][ks], bf, c[0]);
            wmma::mma_sync(c[1], af[1][ks], bf, c[1]);
        }

        // store S to this iteration's buffer; stage next K; ONE barrier
        float* Ss = Sb + cur * (64 * HP);
        wmma::store_matrix_sync(&Ss[(wr * 32) * HP + wc * 16], c[0], HP, wmma::mem_row_major);
        wmma::store_matrix_sync(&Ss[(wr * 32 + 16) * HP + wc * 16], c[1], HP, wmma::mem_row_major);
        if (havenext) {
            *(uint4*)&Kb[(cur ^ 1) * (64 * HP) + r0 * HP + colg] = kreg0;
            *(uint4*)&Kb[(cur ^ 1) * (64 * HP) + (r0 + 32) * HP + colg] = kreg1;
        }
        __syncthreads();

        // epilogue: rows r0 and r0+32
#pragma unroll
        for (int rr = 0; rr < 2; rr++) {
            const int row = r0 + rr * 32;
            float4 s0 = *(float4*)&Ss[row * HP + colg];
            float4 s1 = *(float4*)&Ss[row * HP + colg + 4];
            float e[8];
            e[0] = __expf(fminf(s0.x - 4.f, 10.f)); e[1] = __expf(fminf(s0.y - 4.f, 10.f));
            e[2] = __expf(fminf(s0.z - 4.f, 10.f)); e[3] = __expf(fminf(s0.w - 4.f, 10.f));
            e[4] = __expf(fminf(s1.x - 4.f, 10.f)); e[5] = __expf(fminf(s1.y - 4.f, 10.f));
            e[6] = __expf(fminf(s1.z - 4.f, 10.f)); e[7] = __expf(fminf(s1.w - 4.f, 10.f));
            float psum = 0.f;
#pragma unroll
            for (int j = 0; j < 8; j++) psum += e[j];
            if (rr == 0) zacc0 += psum; else zacc1 += psum;
            __half2 hv[4];
            hv[0] = __floats2half2_rn(e[0], e[1]); hv[1] = __floats2half2_rn(e[2], e[3]);
            hv[2] = __floats2half2_rn(e[4], e[5]); hv[3] = __floats2half2_rn(e[6], e[7]);
            *(uint4*)&g_E[eBase + (size_t)kt * 4096 + row * 64 + colg] = *(uint4*)hv;
        }
    }

    // row-sum reduce over the 8 lanes sharing each row (tid&7 varies cols)
#pragma unroll
    for (int off = 1; off < 8; off <<= 1) {
        zacc0 += __shfl_xor_sync(0xffffffffu, zacc0, off);
        zacc1 += __shfl_xor_sync(0xffffffffu, zacc1, off);
    }
    if ((tid & 7) == 0) {
        long long wsBase = ((long long)(b * NH + h)) * T + qt * 64;
        g_wS[wsBase + r0]      = 1.f / (16.f * zacc0);
        g_wS[wsBase + r0 + 32] = 1.f / (16.f * zacc1);
    }
}

// ============================================================================
// Stage B: per (kc, qt, b) block, KPC k-tiles: P = sum_h E_h * wS_h,
// write attn (fp32), partial O = P V -> g_Opart[kc]. 512 thr.
// ============================================================================
__global__ __launch_bounds__(512, 2) void attn_combine(float* __restrict__ attn)
{
    __shared__ __align__(16) char smraw[9216 + 9216 + 18432 + 4096];
    __half* Ps = (__half*)smraw;
    __half* Vs = (__half*)(smraw + 9216);
    float*  Ss = (float*)(smraw + 18432);
    float*  wSs = (float*)(smraw + 36864);

    const int kc = blockIdx.x;
    const int qt = blockIdx.y;
    const int b  = blockIdx.z;
    const int tid = threadIdx.x;
    const int wid = tid >> 5;
    const int wq = wid >> 2;
    const int wn = wid & 3;
    const int row  = tid >> 3;
    const int colg = (tid & 7) * 8;

    const long long qrow0 = (long long)b * T + qt * 64;
    const size_t eBase = ((size_t)((b * QT + qt) * NH)) * ((size_t)KT * 4096);

#pragma unroll
    for (int i = 0; i < 2; i++) {
        int t = tid + i * 512;
        int h = t >> 6, r = t & 63;
        wSs[t] = g_wS[((long long)(b * NH + h)) * T + qt * 64 + r];
    }
    __syncthreads();

    wmma::fragment<wmma::accumulator, 16, 16, 16, float> co;
    wmma::fill_fragment(co, 0.f);

    for (int ki = 0; ki < KPC; ki++) {
        const int kt = kc * KPC + ki;

        uint4 vreg = *(const uint4*)&g_V[((long long)b * T + kt * 64 + row) * HS + colg];

        float acc[8];
#pragma unroll
        for (int j = 0; j < 8; j++) acc[j] = 0.f;
#pragma unroll
        for (int h = 0; h < NH; h++) {
            uint4 e4 = *(const uint4*)&g_E[eBase + ((size_t)h * KT + kt) * 4096 + row * 64 + colg];
            float w = wSs[h * 64 + row];
            __half2* ph = (__half2*)&e4;
#pragma unroll
            for (int j = 0; j < 4; j++) {
                float2 f = __half22float2(ph[j]);
                acc[2 * j]     = fmaf(f.x, w, acc[2 * j]);
                acc[2 * j + 1] = fmaf(f.y, w, acc[2 * j + 1]);
            }
        }

        float* arow = &attn[(qrow0 + row) * T + kt * 64 + colg];
        *(float4*)&arow[0] = make_float4(acc[0], acc[1], acc[2], acc[3]);
        *(float4*)&arow[4] = make_float4(acc[4], acc[5], acc[6], acc[7]);

        __half2 pv[4];
        pv[0] = __floats2half2_rn(acc[0], acc[1]); pv[1] = __floats2half2_rn(acc[2], acc[3]);
        pv[2] = __floats2half2_rn(acc[4], acc[5]); pv[3] = __floats2half2_rn(acc[6], acc[7]);

        __syncthreads();
        *(uint4*)&Ps[row * HP + colg] = *(uint4*)pv;
        *(uint4*)&Vs[row * HP + colg] = vreg;
        __syncthreads();

#pragma unroll
        for (int ks = 0; ks < 4; ks++) {
            wmma::fragment<wmma::matrix_a, 16, 16, 16, __half, wmma::row_major> pa;
            wmma::fragment<wmma::matrix_b, 16, 16, 16, __half, wmma::row_major> vb;
            wmma::load_matrix_sync(pa, &Ps[(wq * 16) * HP + ks * 16], HP);
            wmma::load_matrix_sync(vb, &Vs[(ks * 16) * HP + wn * 16], HP);
            wmma::mma_sync(co, pa, vb, co);
        }
    }

    __syncthreads();
    wmma::store_matrix_sync(&Ss[(wq * 16) * HP + wn * 16], co, HP, wmma::mem_row_major);
    __syncthreads();
    float* dst = &g_Opart[(size_t)kc * PSLICE + (qrow0 + row) * HS + colg];
    *(float4*)&dst[0] = *(float4*)&Ss[row * HP + colg];
    *(float4*)&dst[4] = *(float4*)&Ss[row * HP + colg + 4];
}

// ============================================================================
// Launch
// ============================================================================
extern "C" void kernel_launch(void* const* d_in, const int* in_sizes, int n_in,
                              void* d_out, int out_size)
{
    const float* x  = (const float*)d_in[0];
    const float* Wq = (const float*)d_in[1];
    const float* bq = (const float*)d_in[2];
    const float* Wk = (const float*)d_in[3];
    const float* bk = (const float*)d_in[4];
    const float* Wv = (const float*)d_in[5];
    const float* bv = (const float*)d_in[6];
    const float* Wo = (const float*)d_in[7];
    const float* bo = (const float*)d_in[8];

    float* out  = (float*)d_out;
    float* attn = out + OUT_ELEMS;

    __half *xh, *Wqh, *Wkh, *Wvh, *Woh, *Qp, *Kp, *Vp, *Orp;
    float *Op;
    cudaGetSymbolAddress((void**)&xh,  g_xh);
    cudaGetSymbolAddress((void**)&Wqh, g_Wqh);
    cudaGetSymbolAddress((void**)&Wkh, g_Wkh);
    cudaGetSymbolAddress((void**)&Wvh, g_Wvh);
    cudaGetSymbolAddress((void**)&Woh, g_Woh);
    cudaGetSymbolAddress((void**)&Qp,  g_Q);
    cudaGetSymbolAddress((void**)&Kp,  g_K);
    cudaGetSymbolAddress((void**)&Vp,  g_V);
    cudaGetSymbolAddress((void**)&Op,  g_Opart);
    cudaGetSymbolAddress((void**)&Orp, g_Ored);

    cudaFuncSetAttribute(gemm_f16_v2, cudaFuncAttributeMaxDynamicSharedMemorySize,
                         GEMM_SMEM);
    cudaFuncSetAttribute(attn_scores, cudaFuncAttributeMaxDynamicSharedMemorySize,
                         ASA_SMEM);

    // conversions (single kernel)
    conv_all<<<2048, 256>>>(x, Wq, Wk, Wv, Wo);

    // projections (fp16 MMA, fp32 accum; Q pre-scaled by HS^-0.5)
    gemm_f16_v2<<<dim3(HID / 128, (B * T) / 128), 256, GEMM_SMEM>>>(
        xh, Wqh, bq, Qp, nullptr, 0.125f, B * T, HID, HID);
    gemm_f16_v2<<<dim3(HID / 128, (B * T) / 128), 256, GEMM_SMEM>>>(
        xh, Wkh, bk, Kp, nullptr, 1.0f, B * T, HID, HID);
    gemm_f16_v2<<<dim3(1, (B * T) / 128), 256, GEMM_SMEM>>>(
        xh, Wvh, bv, Vp, nullptr, 1.0f, B * T, HS, HID);

    // stage A: scores -> E + row sums (tall warp tiles, 256 thr)
    attn_scores<<<dim3(QT, NH, B), 256, ASA_SMEM>>>();

    // stage B: head-average -> attn + partial O
    attn_combine<<<dim3(KC, QT, B), 512>>>(attn);

    // reduce partials -> fp16 O
    reduceN_f16<<<(int)((PSLICE / 4 + 255) / 256), 256>>>(Op);

    // out = O @ Wo + bo  (fp16 MMA, fp32 out)
    gemm_f16_v2<<<dim3(HID / 128, (B * T) / 128), 256, GEMM_SMEM>>>(
        Orp, Woh, bo, nullptr, out, 1.0f, B * T, HID, HS);
}

// round 11
// speedup vs baseline: 1.0667x; 1.0667x over previous
#include <cuda_runtime.h>
#include <cuda_fp16.h>
#include <mma.h>
#include <cstdint>

using namespace nvcuda;

namespace {
constexpr int B   = 4;
constexpr int T   = 2048;
constexpr int HID = 1024;
constexpr int NH  = 16;
constexpr int HS  = 64;
constexpr long long OUT_ELEMS = (long long)B * T * HID;
constexpr int QT  = T / 64;
constexpr int KT  = T / 64;
constexpr int KC  = 8;              // k-chunks in stage B
constexpr int KPC = KT / KC;        // 4 k-tiles per chunk
constexpr int HP  = 72;             // attention smem pitch (halves/floats)
constexpr long long PSLICE = (long long)B * T * HS;

// packed QKV projection: cols [0,1024) = Q*0.125, [1024,2048) = K,
// [2048,2112) = V, [2112,2176) = zero pad. 2176 = 17*128.
constexpr int QKVP = 2176;
constexpr int VOFF = 2048;

// gemm tiling
constexpr int GP  = 40;             // As pitch (halves): 32 + 8
constexpr int GBP = 136;            // Bs pitch (halves): 128 + 8
constexpr int CPF = 136;            // Cs pitch (floats)
constexpr int BUF_BYTES = 128 * GP * 2 + 32 * GBP * 2;  // 18944
constexpr int NSTAGE = 3;
constexpr int GEMM_SMEM = 128 * CPF * 4;                // 69632 (>= 3*BUF_BYTES)

// stage A smem: Qs 9216 | Kb 2x9216 | Ss 2x18432  = 64512
constexpr int ASA_SMEM = 9216 + 2 * 9216 + 2 * 18432;
}

// ---- scratch (static device globals) ----
__device__ __half g_xh[(size_t)B * T * HID];
__device__ __half g_Wpk[(size_t)HID * QKVP];     // packed [0.125Wq | Wk | Wv | 0]
__device__ float  g_bpk[QKVP];                   // packed bias
__device__ __half g_Woh[(size_t)HS * HID];
__device__ __half g_QKV[(size_t)B * T * QKVP];   // packed Q(pre-scaled)/K/V
__device__ float  g_wS[(size_t)B * NH * T];      // 1/(16*Z)
__device__ float  g_Opart[(size_t)KC * B * T * HS];
__device__ __half g_Ored[(size_t)B * T * HS];
__device__ __half g_E[(size_t)B * NH * T * T];   // exp(s-4)

// ---- cp.async helpers ----
__device__ __forceinline__ void cp_async16(unsigned int dst, const void* src, int src_bytes) {
    asm volatile("cp.async.ca.shared.global [%0], [%1], 16, %2;\n"
                 :: "r"(dst), "l"(src), "r"(src_bytes));
}
__device__ __forceinline__ void cp_commit() {
    asm volatile("cp.async.commit_group;\n" ::: "memory");
}
template<int N>
__device__ __forceinline__ void cp_wait() {
    asm volatile("cp.async.wait_group %0;\n" :: "n"(N) : "memory");
}
__device__ __forceinline__ unsigned int smem_addr(const void* p) {
    return (unsigned int)__cvta_generic_to_shared(p);
}

__device__ __forceinline__ uint2 pack_h4(float a, float b, float c, float d) {
    __half2 h0 = __floats2half2_rn(a, b);
    __half2 h1 = __floats2half2_rn(c, d);
    uint2 u;
    u.x = *(unsigned int*)&h0;
    u.y = *(unsigned int*)&h1;
    return u;
}

// ============================================================================
// Conversion + weight packing (grid-stride over float4 groups).
// x -> g_xh; 0.125*Wq, Wk, Wv -> g_Wpk (packed cols); Wo -> g_Woh;
// zero-pad cols [2112,2176); block 0 also fills g_bpk.
// ============================================================================
__global__ void conv_pack(const float* __restrict__ x,  const float* __restrict__ wq,
                          const float* __restrict__ bq,
                          const float* __restrict__ wk, const float* __restrict__ bk,
                          const float* __restrict__ wv, const float* __restrict__ bv,
                          const float* __restrict__ wo)
{
    constexpr int NX  = (B * T * HID) / 4;     // x
    constexpr int NW  = (HID * HID) / 4;       // wq / wk
    constexpr int NV  = (HID * HS) / 4;        // wv
    constexpr int NO  = (HS * HID) / 4;        // wo
    constexpr int NP  = (HID * HS) / 4;        // zero pad
    constexpr int TOT = NX + 2 * NW + NV + NO + NP;

    if (blockIdx.x == 0) {
        for (int i = threadIdx.x; i < QKVP; i += blockDim.x) {
            float v;
            if (i < 1024)      v = 0.125f * bq[i];
            else if (i < 2048) v = bk[i - 1024];
            else if (i < 2112) v = bv[i - 2048];
            else               v = 0.f;
            g_bpk[i] = v;
        }
    }

    for (int i = blockIdx.x * blockDim.x + threadIdx.x; i < TOT;
         i += gridDim.x * blockDim.x) {
        if (i < NX) {
            float4 v = ((const float4*)x)[i];
            ((uint2*)g_xh)[i] = pack_h4(v.x, v.y, v.z, v.w);
        } else if (i < NX + NW) {
            int f = i - NX;                     // wq: 256 float4 per k-row
            int k = f >> 8, n = (f & 255) * 4;
            float4 v = ((const float4*)wq)[f];
            *(uint2*)&g_Wpk[(size_t)k * QKVP + n] =
                pack_h4(0.125f * v.x, 0.125f * v.y, 0.125f * v.z, 0.125f * v.w);
        } else if (i < NX + 2 * NW) {
            int f = i - NX - NW;                // wk
            int k = f >> 8, n = (f & 255) * 4;
            float4 v = ((const float4*)wk)[f];
            *(uint2*)&g_Wpk[(size_t)k * QKVP + 1024 + n] = pack_h4(v.x, v.y, v.z, v.w);
        } else if (i < NX + 2 * NW + NV) {
            int f = i - NX - 2 * NW;            // wv: 16 float4 per k-row
            int k = f >> 4, n = (f & 15) * 4;
            float4 v = ((const float4*)wv)[f];
            *(uint2*)&g_Wpk[(size_t)k * QKVP + VOFF + n] = pack_h4(v.x, v.y, v.z, v.w);
        } else if (i < NX + 2 * NW + NV + NO) {
            int f = i - NX - 2 * NW - NV;       // wo (dense)
            float4 v = ((const float4*)wo)[f];
            ((uint2*)g_Woh)[f] = pack_h4(v.x, v.y, v.z, v.w);
        } else {
            int f = i - NX - 2 * NW - NV - NO;  // zero pad cols [2112,2176)
            int k = f >> 4, n = (f & 15) * 4;
            uint2 z; z.x = 0u; z.y = 0u;
            *(uint2*)&g_Wpk[(size_t)k * QKVP + 2112 + n] = z;
        }
    }
}

// ============================================================================
// Reduce KC Opart fp32 slices -> fp16 g_Ored
// ============================================================================
__global__ void reduceN_f16(const float* __restrict__ A)
{
    int i = blockIdx.x * blockDim.x + threadIdx.x;   // float4 index
    constexpr int N4 = (int)(PSLICE / 4);
    if (i < N4) {
        float4 v = ((const float4*)A)[i];
#pragma unroll
        for (int p = 1; p < KC; p++) {
            float4 w = ((const float4*)(A + p * PSLICE))[i];
            v.x += w.x; v.y += w.y; v.z += w.z; v.w += w.w;
        }
        ((uint2*)g_Ored)[i] = pack_h4(v.x, v.y, v.z, v.w);
    }
}

// ============================================================================
// fp16 GEMM: C[M,N] = A[M,K] @ W[K,N] (+bias). BM=128, BN=128, BK=32,
// cp.async 3-stage pipeline. 256 thr, 8 warps (4x2), warp tile 32x64.
// Output fp16 (Ch) or fp32 (Cf). Requires N % 128 == 0, K % 32 == 0.
// ============================================================================
__global__ __launch_bounds__(256, 2) void gemm_f16_v2(
    const __half* __restrict__ A, const __half* __restrict__ W,
    const float* __restrict__ bias, __half* __restrict__ Ch,
    float* __restrict__ Cf, int M, int N, int K)
{
    extern __shared__ char dsm[];

    const int tid = threadIdx.x;
    const int wid = tid >> 5;
    const int wq = wid >> 1;
    const int wn = wid & 1;
    const long long row0 = (long long)blockIdx.y * 128;
    const int n0 = blockIdx.x * 128;

    wmma::fragment<wmma::accumulator, 16, 16, 16, float> c[2][4];
#pragma unroll
    for (int i = 0; i < 2; i++)
#pragma unroll
        for (int j = 0; j < 4; j++) wmma::fill_fragment(c[i][j], 0.f);

    const int nkb = K / 32;

    auto issue = [&](int kb) {
        const int k0 = kb * 32;
        char* base = dsm + (kb % NSTAGE) * BUF_BYTES;
        __half* As = (__half*)base;
        __half* Bs = (__half*)(base + 128 * GP * 2);
#pragma unroll
        for (int i = 0; i < 2; i++) {
            int ci = tid + i * 256;
            int r = ci >> 2, off = (ci & 3) * 8;
            cp_async16(smem_addr(&As[r * GP + off]),
                       &A[(row0 + r) * K + k0 + off], 16);
        }
#pragma unroll
        for (int i = 0; i < 2; i++) {
            int ci = tid + i * 256;
            int r = ci >> 4, off = (ci & 15) * 8;
            cp_async16(smem_addr(&Bs[r * GBP + off]),
                       &W[(long long)(k0 + r) * N + n0 + off], 16);
        }
        cp_commit();
    };

    issue(0);
    if (nkb > 1) issue(1);

    for (int kb = 0; kb < nkb; kb++) {
        if (kb + 2 < nkb) {
            issue(kb + 2);
            cp_wait<2>();
        } else if (kb + 1 < nkb) {
            cp_wait<1>();
        } else {
            cp_wait<0>();
        }
        __syncthreads();

        char* base = dsm + (kb % NSTAGE) * BUF_BYTES;
        __half* As = (__half*)base;
        __half* Bs = (__half*)(base + 128 * GP * 2);

#pragma unroll
        for (int ks = 0; ks < 2; ks++) {
            wmma::fragment<wmma::matrix_a, 16, 16, 16, __half, wmma::row_major> a0, a1;
            wmma::load_matrix_sync(a0, &As[(wq * 32) * GP + ks * 16], GP);
            wmma::load_matrix_sync(a1, &As[(wq * 32 + 16) * GP + ks * 16], GP);
#pragma unroll
            for (int n = 0; n < 4; n++) {
                wmma::fragment<wmma::matrix_b, 16, 16, 16, __half, wmma::row_major> bf;
                wmma::load_matrix_sync(bf, &Bs[(ks * 16) * GBP + wn * 64 + n * 16], GBP);
                wmma::mma_sync(c[0][n], a0, bf, c[0][n]);
                wmma::mma_sync(c[1][n], a1, bf, c[1][n]);
            }
        }
        __syncthreads();
    }

    // epilogue through smem
    float* Cs = (float*)dsm;                 // [128][CPF]
#pragma unroll
    for (int i = 0; i < 2; i++)
#pragma unroll
        for (int j = 0; j < 4; j++)
            wmma::store_matrix_sync(&Cs[(wq * 32 + i * 16) * CPF + wn * 64 + j * 16],
                                    c[i][j], CPF, wmma::mem_row_major);
    __syncthreads();

#pragma unroll
    for (int i = 0; i < 16; i++) {
        int idx = tid + i * 256;
        int r = idx >> 5, c4 = (idx & 31) * 4;
        int col = n0 + c4;
        float4 v = *(float4*)&Cs[r * CPF + c4];
        v.x += bias[col];     v.y += bias[col + 1];
        v.z += bias[col + 2]; v.w += bias[col + 3];
        if (Cf) {
            *(float4*)&Cf[(row0 + r) * N + col] = v;
        } else {
            *(uint2*)&Ch[(row0 + r) * N + col] = pack_h4(v.x, v.y, v.z, v.w);
        }
    }
}

// ============================================================================
// Stage A (R9 config): per (qt, h, b) block, S = Q_h K_h^T over all kt,
// E = exp(s-4) -> g_E (fp16), row sums -> g_wS. 512 thr.
// K and S double-buffered; ONE barrier per k-tile.
// Reads packed g_QKV (row stride QKVP; K at col offset 1024).
// Dynamic smem: Qs 9216 | Kb 2x9216 | Ss 2x18432 = 64512 B.
// ============================================================================
__global__ __launch_bounds__(512, 2) void attn_scores()
{
    extern __shared__ char smraw[];
    __half* Qs = (__half*)smraw;                    // [64][HP]
    __half* Kb = Qs + 64 * HP;                      // 2 x [64][HP]
    float*  Sb = (float*)(smraw + 9216 + 18432);    // 2 x [64][HP] fp32

    const int qt = blockIdx.x;
    const int h  = blockIdx.y;
    const int b  = blockIdx.z;
    const int tid = threadIdx.x;
    const int wid = tid >> 5;
    const int wq = wid >> 2;
    const int wn = wid & 3;
    const int row  = tid >> 3;
    const int colg = (tid & 7) * 8;

    const long long qrow0 = (long long)b * T + qt * 64;
    const long long krow0 = (long long)b * T;
    const size_t eBase = ((size_t)((b * QT + qt) * NH) + h) * ((size_t)KT * 4096);

    *(uint4*)&Qs[row * HP + colg] =
        *(const uint4*)&g_QKV[(qrow0 + row) * QKVP + h * 64 + colg];
    *(uint4*)&Kb[row * HP + colg] =
        *(const uint4*)&g_QKV[(krow0 + row) * QKVP + 1024 + h * 64 + colg];
    __syncthreads();

    wmma::fragment<wmma::matrix_a, 16, 16, 16, __half, wmma::row_major> af[4];
#pragma unroll
    for (int ks = 0; ks < 4; ks++)
        wmma::load_matrix_sync(af[ks], &Qs[(wq * 16) * HP + ks * 16], HP);

    float zacc = 0.f;

    for (int kt = 0; kt < KT; kt++) {
        const int cur = kt & 1;
        uint4 kreg;
        const bool havenext = (kt + 1) < KT;
        if (havenext)
            kreg = *(const uint4*)&g_QKV[(krow0 + (kt + 1) * 64 + row) * QKVP + 1024 + h * 64 + colg];

        wmma::fragment<wmma::accumulator, 16, 16, 16, float> c;
        wmma::fill_fragment(c, 0.f);
        const __half* Kc = Kb + cur * (64 * HP);
#pragma unroll
        for (int ks = 0; ks < 4; ks++) {
            wmma::fragment<wmma::matrix_b, 16, 16, 16, __half, wmma::col_major> bf;
            wmma::load_matrix_sync(bf, &Kc[(wn * 16) * HP + ks * 16], HP);
            wmma::mma_sync(c, af[ks], bf, c);
        }

        // store S into this iteration's buffer; stage next K; ONE barrier
        float* Ss = Sb + cur * (64 * HP);
        wmma::store_matrix_sync(&Ss[(wq * 16) * HP + wn * 16], c, HP, wmma::mem_row_major);
        if (havenext)
            *(uint4*)&Kb[(cur ^ 1) * (64 * HP) + row * HP + colg] = kreg;
        __syncthreads();

        float4 s0 = *(float4*)&Ss[row * HP + colg];
        float4 s1 = *(float4*)&Ss[row * HP + colg + 4];
        float e[8];
        e[0] = __expf(fminf(s0.x - 4.f, 10.f)); e[1] = __expf(fminf(s0.y - 4.f, 10.f));
        e[2] = __expf(fminf(s0.z - 4.f, 10.f)); e[3] = __expf(fminf(s0.w - 4.f, 10.f));
        e[4] = __expf(fminf(s1.x - 4.f, 10.f)); e[5] = __expf(fminf(s1.y - 4.f, 10.f));
        e[6] = __expf(fminf(s1.z - 4.f, 10.f)); e[7] = __expf(fminf(s1.w - 4.f, 10.f));
#pragma unroll
        for (int j = 0; j < 8; j++) zacc += e[j];
        __half2 hv[4];
        hv[0] = __floats2half2_rn(e[0], e[1]); hv[1] = __floats2half2_rn(e[2], e[3]);
        hv[2] = __floats2half2_rn(e[4], e[5]); hv[3] = __floats2half2_rn(e[6], e[7]);
        *(uint4*)&g_E[eBase + (size_t)kt * 4096 + row * 64 + colg] = *(uint4*)hv;
    }

    float z = zacc;
#pragma unroll
    for (int off = 1; off < 8; off <<= 1)
        z += __shfl_xor_sync(0xffffffffu, z, off);
    if ((tid & 7) == 0)
        g_wS[((long long)(b * NH + h)) * T + qt * 64 + row] = 1.f / (16.f * z);
}

// ============================================================================
// Stage B: per (kc, qt, b) block, KPC k-tiles: P = sum_h E_h * wS_h,
// write attn (fp32), partial O = P V -> g_Opart[kc]. 512 thr.
// V read from packed g_QKV at col offset VOFF.
// ============================================================================
__global__ __launch_bounds__(512, 2) void attn_combine(float* __restrict__ attn)
{
    __shared__ __align__(16) char smraw[9216 + 9216 + 18432 + 4096];
    __half* Ps = (__half*)smraw;
    __half* Vs = (__half*)(smraw + 9216);
    float*  Ss = (float*)(smraw + 18432);
    float*  wSs = (float*)(smraw + 36864);

    const int kc = blockIdx.x;
    const int qt = blockIdx.y;
    const int b  = blockIdx.z;
    const int tid = threadIdx.x;
    const int wid = tid >> 5;
    const int wq = wid >> 2;
    const int wn = wid & 3;
    const int row  = tid >> 3;
    const int colg = (tid & 7) * 8;

    const long long qrow0 = (long long)b * T + qt * 64;
    const size_t eBase = ((size_t)((b * QT + qt) * NH)) * ((size_t)KT * 4096);

#pragma unroll
    for (int i = 0; i < 2; i++) {
        int t = tid + i * 512;
        int h = t >> 6, r = t & 63;
        wSs[t] = g_wS[((long long)(b * NH + h)) * T + qt * 64 + r];
    }
    __syncthreads();

    wmma::fragment<wmma::accumulator, 16, 16, 16, float> co;
    wmma::fill_fragment(co, 0.f);

    for (int ki = 0; ki < KPC; ki++) {
        const int kt = kc * KPC + ki;

        uint4 vreg = *(const uint4*)&g_QKV[((long long)b * T + kt * 64 + row) * QKVP + VOFF + colg];

        float acc[8];
#pragma unroll
        for (int j = 0; j < 8; j++) acc[j] = 0.f;
#pragma unroll
        for (int h = 0; h < NH; h++) {
            uint4 e4 = *(const uint4*)&g_E[eBase + ((size_t)h * KT + kt) * 4096 + row * 64 + colg];
            float w = wSs[h * 64 + row];
            __half2* ph = (__half2*)&e4;
#pragma unroll
            for (int j = 0; j < 4; j++) {
                float2 f = __half22float2(ph[j]);
                acc[2 * j]     = fmaf(f.x, w, acc[2 * j]);
                acc[2 * j + 1] = fmaf(f.y, w, acc[2 * j + 1]);
            }
        }

        float* arow = &attn[(qrow0 + row) * T + kt * 64 + colg];
        *(float4*)&arow[0] = make_float4(acc[0], acc[1], acc[2], acc[3]);
        *(float4*)&arow[4] = make_float4(acc[4], acc[5], acc[6], acc[7]);

        __half2 pv[4];
        pv[0] = __floats2half2_rn(acc[0], acc[1]); pv[1] = __floats2half2_rn(acc[2], acc[3]);
        pv[2] = __floats2half2_rn(acc[4], acc[5]); pv[3] = __floats2half2_rn(acc[6], acc[7]);

        __syncthreads();
        *(uint4*)&Ps[row * HP + colg] = *(uint4*)pv;
        *(uint4*)&Vs[row * HP + colg] = vreg;
        __syncthreads();

#pragma unroll
        for (int ks = 0; ks < 4; ks++) {
            wmma::fragment<wmma::matrix_a, 16, 16, 16, __half, wmma::row_major> pa;
            wmma::fragment<wmma::matrix_b, 16, 16, 16, __half, wmma::row_major> vb;
            wmma::load_matrix_sync(pa, &Ps[(wq * 16) * HP + ks * 16], HP);
            wmma::load_matrix_sync(vb, &Vs[(ks * 16) * HP + wn * 16], HP);
            wmma::mma_sync(co, pa, vb, co);
        }
    }

    __syncthreads();
    wmma::store_matrix_sync(&Ss[(wq * 16) * HP + wn * 16], co, HP, wmma::mem_row_major);
    __syncthreads();
    float* dst = &g_Opart[(size_t)kc * PSLICE + (qrow0 + row) * HS + colg];
    *(float4*)&dst[0] = *(float4*)&Ss[row * HP + colg];
    *(float4*)&dst[4] = *(float4*)&Ss[row * HP + colg + 4];
}

// ============================================================================
// Launch
// ============================================================================
extern "C" void kernel_launch(void* const* d_in, const int* in_sizes, int n_in,
                              void* d_out, int out_size)
{
    const float* x  = (const float*)d_in[0];
    const float* Wq = (const float*)d_in[1];
    const float* bq = (const float*)d_in[2];
    const float* Wk = (const float*)d_in[3];
    const float* bk = (const float*)d_in[4];
    const float* Wv = (const float*)d_in[5];
    const float* bv = (const float*)d_in[6];
    const float* Wo = (const float*)d_in[7];
    const float* bo = (const float*)d_in[8];

    float* out  = (float*)d_out;
    float* attn = out + OUT_ELEMS;

    __half *xh, *Wpk, *Woh, *QKVp, *Orp;
    float *Op, *bpk;
    cudaGetSymbolAddress((void**)&xh,   g_xh);
    cudaGetSymbolAddress((void**)&Wpk,  g_Wpk);
    cudaGetSymbolAddress((void**)&bpk,  g_bpk);
    cudaGetSymbolAddress((void**)&Woh,  g_Woh);
    cudaGetSymbolAddress((void**)&QKVp, g_QKV);
    cudaGetSymbolAddress((void**)&Op,   g_Opart);
    cudaGetSymbolAddress((void**)&Orp,  g_Ored);

    cudaFuncSetAttribute(gemm_f16_v2, cudaFuncAttributeMaxDynamicSharedMemorySize,
                         GEMM_SMEM);
    cudaFuncSetAttribute(attn_scores, cudaFuncAttributeMaxDynamicSharedMemorySize,
                         ASA_SMEM);

    // 1. conversions + weight packing
    conv_pack<<<2048, 256>>>(x, Wq, bq, Wk, bk, Wv, bv, Wo);

    // 2. fused QKV projection: [8192 x 2176] = xh @ Wpk + bpk (fp16 out)
    gemm_f16_v2<<<dim3(QKVP / 128, (B * T) / 128), 256, GEMM_SMEM>>>(
        xh, Wpk, bpk, QKVp, nullptr, B * T, QKVP, HID);

    // 3. stage A: scores -> E + row sums
    attn_scores<<<dim3(QT, NH, B), 512, ASA_SMEM>>>();

    // 4. stage B: head-average -> attn + partial O (profiled slot)
    attn_combine<<<dim3(KC, QT, B), 512>>>(attn);

    // 5. reduce partials -> fp16 O
    reduceN_f16<<<(int)((PSLICE / 4 + 255) / 256), 256>>>(Op);

    // 6. out = O @ Wo + bo  (fp16 MMA, fp32 out)
    gemm_f16_v2<<<dim3(HID / 128, (B * T) / 128), 256, GEMM_SMEM>>>(
        Orp, Woh, bo, nullptr, out, B * T, HID, HS);
}

// round 12
// speedup vs baseline: 1.1208x; 1.0507x over previous
#include <cuda_runtime.h>
#include <cuda_fp16.h>
#include <mma.h>
#include <cstdint>

using namespace nvcuda;

namespace {
constexpr int B   = 4;
constexpr int T   = 2048;
constexpr int HID = 1024;
constexpr int NH  = 16;
constexpr int HS  = 64;
constexpr long long OUT_ELEMS = (long long)B * T * HID;
constexpr int QT  = T / 64;
constexpr int KT  = T / 64;
constexpr int KC  = 8;              // k-chunks in stage B
constexpr int KPC = KT / KC;        // 4 k-tiles per chunk
constexpr int HP  = 72;             // attention smem pitch (halves/floats)
constexpr long long PSLICE = (long long)B * T * HS;

// packed QKV projection: cols [0,1024) = Q*0.125, [1024,2048) = K,
// [2048,2112) = V, [2112,2176) = zero pad. 2176 = 17*128.
constexpr int QKVP = 2176;
constexpr int VOFF = 2048;

// gemm tiling: BM=128, BN=128, BK=64, 2-stage cp.async
constexpr int GP  = 72;             // As pitch (halves): 64 + 8
constexpr int GBP = 136;            // Bs pitch (halves): 128 + 8
constexpr int CPF = 136;            // Cs pitch (floats)
constexpr int BUF_BYTES = 128 * GP * 2 + 64 * GBP * 2;  // 18432 + 17408 = 35840
constexpr int NSTAGE = 2;
constexpr int GEMM_SMEM = 2 * BUF_BYTES;                // 71680 (> epilogue 69632)

// stage A smem: Qs 9216 | Kb 2x9216 | Ss 2x18432  = 64512
constexpr int ASA_SMEM = 9216 + 2 * 9216 + 2 * 18432;

// combine smem: Ps 2x9216 | Vs 2x9216 | Ss 18432 | wSs 4096 = 59392
constexpr int ACB_SMEM = 4 * 9216 + 18432 + 4096;
}

// ---- scratch (static device globals) ----
__device__ __half g_xh[(size_t)B * T * HID];
__device__ __half g_Wpk[(size_t)HID * QKVP];     // packed [0.125Wq | Wk | Wv | 0]
__device__ float  g_bpk[QKVP];                   // packed bias
__device__ __half g_Woh[(size_t)HS * HID];
__device__ __half g_QKV[(size_t)B * T * QKVP];   // packed Q(pre-scaled)/K/V
__device__ float  g_wS[(size_t)B * NH * T];      // 1/(16*Z)
__device__ float  g_Opart[(size_t)KC * B * T * HS];
__device__ __half g_Ored[(size_t)B * T * HS];
__device__ __half g_E[(size_t)B * NH * T * T];   // exp(s-4)

// ---- cp.async helpers ----
__device__ __forceinline__ void cp_async16(unsigned int dst, const void* src) {
    asm volatile("cp.async.ca.shared.global [%0], [%1], 16;\n"
                 :: "r"(dst), "l"(src));
}
__device__ __forceinline__ void cp_commit() {
    asm volatile("cp.async.commit_group;\n" ::: "memory");
}
template<int N>
__device__ __forceinline__ void cp_wait() {
    asm volatile("cp.async.wait_group %0;\n" :: "n"(N) : "memory");
}
__device__ __forceinline__ unsigned int smem_addr(const void* p) {
    return (unsigned int)__cvta_generic_to_shared(p);
}

__device__ __forceinline__ uint2 pack_h4(float a, float b, float c, float d) {
    __half2 h0 = __floats2half2_rn(a, b);
    __half2 h1 = __floats2half2_rn(c, d);
    uint2 u;
    u.x = *(unsigned int*)&h0;
    u.y = *(unsigned int*)&h1;
    return u;
}

// ============================================================================
// Conversion + weight packing (grid-stride over float4 groups).
// ============================================================================
__global__ void conv_pack(const float* __restrict__ x,  const float* __restrict__ wq,
                          const float* __restrict__ bq,
                          const float* __restrict__ wk, const float* __restrict__ bk,
                          const float* __restrict__ wv, const float* __restrict__ bv,
                          const float* __restrict__ wo)
{
    constexpr int NX  = (B * T * HID) / 4;
    constexpr int NW  = (HID * HID) / 4;
    constexpr int NV  = (HID * HS) / 4;
    constexpr int NO  = (HS * HID) / 4;
    constexpr int NP  = (HID * HS) / 4;
    constexpr int TOT = NX + 2 * NW + NV + NO + NP;

    if (blockIdx.x == 0) {
        for (int i = threadIdx.x; i < QKVP; i += blockDim.x) {
            float v;
            if (i < 1024)      v = 0.125f * bq[i];
            else if (i < 2048) v = bk[i - 1024];
            else if (i < 2112) v = bv[i - 2048];
            else               v = 0.f;
            g_bpk[i] = v;
        }
    }

    for (int i = blockIdx.x * blockDim.x + threadIdx.x; i < TOT;
         i += gridDim.x * blockDim.x) {
        if (i < NX) {
            float4 v = ((const float4*)x)[i];
            ((uint2*)g_xh)[i] = pack_h4(v.x, v.y, v.z, v.w);
        } else if (i < NX + NW) {
            int f = i - NX;
            int k = f >> 8, n = (f & 255) * 4;
            float4 v = ((const float4*)wq)[f];
            *(uint2*)&g_Wpk[(size_t)k * QKVP + n] =
                pack_h4(0.125f * v.x, 0.125f * v.y, 0.125f * v.z, 0.125f * v.w);
        } else if (i < NX + 2 * NW) {
            int f = i - NX - NW;
            int k = f >> 8, n = (f & 255) * 4;
            float4 v = ((const float4*)wk)[f];
            *(uint2*)&g_Wpk[(size_t)k * QKVP + 1024 + n] = pack_h4(v.x, v.y, v.z, v.w);
        } else if (i < NX + 2 * NW + NV) {
            int f = i - NX - 2 * NW;
            int k = f >> 4, n = (f & 15) * 4;
            float4 v = ((const float4*)wv)[f];
            *(uint2*)&g_Wpk[(size_t)k * QKVP + VOFF + n] = pack_h4(v.x, v.y, v.z, v.w);
        } else if (i < NX + 2 * NW + NV + NO) {
            int f = i - NX - 2 * NW - NV;
            float4 v = ((const float4*)wo)[f];
            ((uint2*)g_Woh)[f] = pack_h4(v.x, v.y, v.z, v.w);
        } else {
            int f = i - NX - 2 * NW - NV - NO;
            int k = f >> 4, n = (f & 15) * 4;
            uint2 z; z.x = 0u; z.y = 0u;
            *(uint2*)&g_Wpk[(size_t)k * QKVP + 2112 + n] = z;
        }
    }
}

// ============================================================================
// Reduce KC Opart fp32 slices -> fp16 g_Ored
// ============================================================================
__global__ void reduceN_f16(const float* __restrict__ A)
{
    int i = blockIdx.x * blockDim.x + threadIdx.x;
    constexpr int N4 = (int)(PSLICE / 4);
    if (i < N4) {
        float4 v = ((const float4*)A)[i];
#pragma unroll
        for (int p = 1; p < KC; p++) {
            float4 w = ((const float4*)(A + p * PSLICE))[i];
            v.x += w.x; v.y += w.y; v.z += w.z; v.w += w.w;
        }
        ((uint2*)g_Ored)[i] = pack_h4(v.x, v.y, v.z, v.w);
    }
}

// ============================================================================
// fp16 GEMM: C[M,N] = A[M,K] @ W[K,N] (+bias). BM=128, BN=128, BK=64,
// cp.async 2-stage. 256 thr, 8 warps (4x2), warp tile 32x64.
// Output fp16 (Ch) or fp32 (Cf). Requires N % 128 == 0, K % 64 == 0.
// ============================================================================
__global__ __launch_bounds__(256, 2) void gemm_f16_v2(
    const __half* __restrict__ A, const __half* __restrict__ W,
    const float* __restrict__ bias, __half* __restrict__ Ch,
    float* __restrict__ Cf, int M, int N, int K)
{
    extern __shared__ char dsm[];

    const int tid = threadIdx.x;
    const int wid = tid >> 5;
    const int wq = wid >> 1;
    const int wn = wid & 1;
    const long long row0 = (long long)blockIdx.y * 128;
    const int n0 = blockIdx.x * 128;

    wmma::fragment<wmma::accumulator, 16, 16, 16, float> c[2][4];
#pragma unroll
    for (int i = 0; i < 2; i++)
#pragma unroll
        for (int j = 0; j < 4; j++) wmma::fill_fragment(c[i][j], 0.f);

    const int nkb = K / 64;

    auto issue = [&](int kb) {
        const int k0 = kb * 64;
        char* base = dsm + (kb & 1) * BUF_BYTES;
        __half* As = (__half*)base;
        __half* Bs = (__half*)(base + 128 * GP * 2);
        // A: 128x64 halves = 1024 uint4, 4 per thread
#pragma unroll
        for (int i = 0; i < 4; i++) {
            int ci = tid + i * 256;
            int r = ci >> 3, off = (ci & 7) * 8;
            cp_async16(smem_addr(&As[r * GP + off]),
                       &A[(row0 + r) * K + k0 + off]);
        }
        // B: 64x128 halves = 1024 uint4, 4 per thread
#pragma unroll
        for (int i = 0; i < 4; i++) {
            int ci = tid + i * 256;
            int r = ci >> 4, off = (ci & 15) * 8;
            cp_async16(smem_addr(&Bs[r * GBP + off]),
                       &W[(long long)(k0 + r) * N + n0 + off]);
        }
        cp_commit();
    };

    issue(0);

    for (int kb = 0; kb < nkb; kb++) {
        if (kb + 1 < nkb) {
            issue(kb + 1);
            cp_wait<1>();
        } else {
            cp_wait<0>();
        }
        __syncthreads();

        char* base = dsm + (kb & 1) * BUF_BYTES;
        __half* As = (__half*)base;
        __half* Bs = (__half*)(base + 128 * GP * 2);

#pragma unroll
        for (int ks = 0; ks < 4; ks++) {
            wmma::fragment<wmma::matrix_a, 16, 16, 16, __half, wmma::row_major> a0, a1;
            wmma::load_matrix_sync(a0, &As[(wq * 32) * GP + ks * 16], GP);
            wmma::load_matrix_sync(a1, &As[(wq * 32 + 16) * GP + ks * 16], GP);
#pragma unroll
            for (int n = 0; n < 4; n++) {
                wmma::fragment<wmma::matrix_b, 16, 16, 16, __half, wmma::row_major> bf;
                wmma::load_matrix_sync(bf, &Bs[(ks * 16) * GBP + wn * 64 + n * 16], GBP);
                wmma::mma_sync(c[0][n], a0, bf, c[0][n]);
                wmma::mma_sync(c[1][n], a1, bf, c[1][n]);
            }
        }
        __syncthreads();
    }

    // epilogue through smem
    float* Cs = (float*)dsm;                 // [128][CPF]
#pragma unroll
    for (int i = 0; i < 2; i++)
#pragma unroll
        for (int j = 0; j < 4; j++)
            wmma::store_matrix_sync(&Cs[(wq * 32 + i * 16) * CPF + wn * 64 + j * 16],
                                    c[i][j], CPF, wmma::mem_row_major);
    __syncthreads();

#pragma unroll
    for (int i = 0; i < 16; i++) {
        int idx = tid + i * 256;
        int r = idx >> 5, c4 = (idx & 31) * 4;
        int col = n0 + c4;
        float4 v = *(float4*)&Cs[r * CPF + c4];
        v.x += bias[col];     v.y += bias[col + 1];
        v.z += bias[col + 2]; v.w += bias[col + 3];
        if (Cf) {
            *(float4*)&Cf[(row0 + r) * N + col] = v;
        } else {
            *(uint2*)&Ch[(row0 + r) * N + col] = pack_h4(v.x, v.y, v.z, v.w);
        }
    }
}

// ============================================================================
// Stage A (R9 config, packed QKV inputs): per (qt, h, b) block,
// S = Q_h K_h^T over all kt, E = exp(s-4) -> g_E, row sums -> g_wS. 512 thr.
// K and S double-buffered; ONE barrier per k-tile.
// ============================================================================
__global__ __launch_bounds__(512, 2) void attn_scores()
{
    extern __shared__ char smraw[];
    __half* Qs = (__half*)smraw;                    // [64][HP]
    __half* Kb = Qs + 64 * HP;                      // 2 x [64][HP]
    float*  Sb = (float*)(smraw + 9216 + 18432);    // 2 x [64][HP] fp32

    const int qt = blockIdx.x;
    const int h  = blockIdx.y;
    const int b  = blockIdx.z;
    const int tid = threadIdx.x;
    const int wid = tid >> 5;
    const int wq = wid >> 2;
    const int wn = wid & 3;
    const int row  = tid >> 3;
    const int colg = (tid & 7) * 8;

    const long long qrow0 = (long long)b * T + qt * 64;
    const long long krow0 = (long long)b * T;
    const size_t eBase = ((size_t)((b * QT + qt) * NH) + h) * ((size_t)KT * 4096);

    *(uint4*)&Qs[row * HP + colg] =
        *(const uint4*)&g_QKV[(qrow0 + row) * QKVP + h * 64 + colg];
    *(uint4*)&Kb[row * HP + colg] =
        *(const uint4*)&g_QKV[(krow0 + row) * QKVP + 1024 + h * 64 + colg];
    __syncthreads();

    wmma::fragment<wmma::matrix_a, 16, 16, 16, __half, wmma::row_major> af[4];
#pragma unroll
    for (int ks = 0; ks < 4; ks++)
        wmma::load_matrix_sync(af[ks], &Qs[(wq * 16) * HP + ks * 16], HP);

    float zacc = 0.f;

    for (int kt = 0; kt < KT; kt++) {
        const int cur = kt & 1;
        uint4 kreg;
        const bool havenext = (kt + 1) < KT;
        if (havenext)
            kreg = *(const uint4*)&g_QKV[(krow0 + (kt + 1) * 64 + row) * QKVP + 1024 + h * 64 + colg];

        wmma::fragment<wmma::accumulator, 16, 16, 16, float> c;
        wmma::fill_fragment(c, 0.f);
        const __half* Kc = Kb + cur * (64 * HP);
#pragma unroll
        for (int ks = 0; ks < 4; ks++) {
            wmma::fragment<wmma::matrix_b, 16, 16, 16, __half, wmma::col_major> bf;
            wmma::load_matrix_sync(bf, &Kc[(wn * 16) * HP + ks * 16], HP);
            wmma::mma_sync(c, af[ks], bf, c);
        }

        float* Ss = Sb + cur * (64 * HP);
        wmma::store_matrix_sync(&Ss[(wq * 16) * HP + wn * 16], c, HP, wmma::mem_row_major);
        if (havenext)
            *(uint4*)&Kb[(cur ^ 1) * (64 * HP) + row * HP + colg] = kreg;
        __syncthreads();

        float4 s0 = *(float4*)&Ss[row * HP + colg];
        float4 s1 = *(float4*)&Ss[row * HP + colg + 4];
        float e[8];
        e[0] = __expf(fminf(s0.x - 4.f, 10.f)); e[1] = __expf(fminf(s0.y - 4.f, 10.f));
        e[2] = __expf(fminf(s0.z - 4.f, 10.f)); e[3] = __expf(fminf(s0.w - 4.f, 10.f));
        e[4] = __expf(fminf(s1.x - 4.f, 10.f)); e[5] = __expf(fminf(s1.y - 4.f, 10.f));
        e[6] = __expf(fminf(s1.z - 4.f, 10.f)); e[7] = __expf(fminf(s1.w - 4.f, 10.f));
#pragma unroll
        for (int j = 0; j < 8; j++) zacc += e[j];
        __half2 hv[4];
        hv[0] = __floats2half2_rn(e[0], e[1]); hv[1] = __floats2half2_rn(e[2], e[3]);
        hv[2] = __floats2half2_rn(e[4], e[5]); hv[3] = __floats2half2_rn(e[6], e[7]);
        *(uint4*)&g_E[eBase + (size_t)kt * 4096 + row * 64 + colg] = *(uint4*)hv;
    }

    float z = zacc;
#pragma unroll
    for (int off = 1; off < 8; off <<= 1)
        z += __shfl_xor_sync(0xffffffffu, z, off);
    if ((tid & 7) == 0)
        g_wS[((long long)(b * NH + h)) * T + qt * 64 + row] = 1.f / (16.f * z);
}

// ============================================================================
// Stage B: per (kc, qt, b) block, KPC k-tiles: P = sum_h E_h * wS_h,
// write attn (fp32), partial O = P V -> g_Opart[kc]. 512 thr.
// P/V double-buffered: ONE barrier per k-tile keeps E loads streaming.
// Dynamic smem: Ps 2x9216 | Vs 2x9216 | Ss 18432 | wSs 4096 = 59392.
// ============================================================================
__global__ __launch_bounds__(512, 2) void attn_combine(float* __restrict__ attn)
{
    extern __shared__ char smraw[];
    float* Ss  = (float*)(smraw + 36864);
    float* wSs = (float*)(smraw + 55296);

    const int kc = blockIdx.x;
    const int qt = blockIdx.y;
    const int b  = blockIdx.z;
    const int tid = threadIdx.x;
    const int wid = tid >> 5;
    const int wq = wid >> 2;
    const int wn = wid & 3;
    const int row  = tid >> 3;
    const int colg = (tid & 7) * 8;

    const long long qrow0 = (long long)b * T + qt * 64;
    const size_t eBase = ((size_t)((b * QT + qt) * NH)) * ((size_t)KT * 4096);

#pragma unroll
    for (int i = 0; i < 2; i++) {
        int t = tid + i * 512;
        int h = t >> 6, r = t & 63;
        wSs[t] = g_wS[((long long)(b * NH + h)) * T + qt * 64 + r];
    }
    __syncthreads();

    wmma::fragment<wmma::accumulator, 16, 16, 16, float> co;
    wmma::fill_fragment(co, 0.f);

    for (int ki = 0; ki < KPC; ki++) {
        const int kt = kc * KPC + ki;
        const int buf = ki & 1;
        __half* Ps = (__half*)(smraw + buf * 9216);
        __half* Vs = (__half*)(smraw + 18432 + buf * 9216);

        uint4 vreg = *(const uint4*)&g_QKV[((long long)b * T + kt * 64 + row) * QKVP + VOFF + colg];

        float acc[8];
#pragma unroll
        for (int j = 0; j < 8; j++) acc[j] = 0.f;
#pragma unroll
        for (int h = 0; h < NH; h++) {
            uint4 e4 = *(const uint4*)&g_E[eBase + ((size_t)h * KT + kt) * 4096 + row * 64 + colg];
            float w = wSs[h * 64 + row];
            __half2* ph = (__half2*)&e4;
#pragma unroll
            for (int j = 0; j < 4; j++) {
                float2 f = __half22float2(ph[j]);
                acc[2 * j]     = fmaf(f.x, w, acc[2 * j]);
                acc[2 * j + 1] = fmaf(f.y, w, acc[2 * j + 1]);
            }
        }

        float* arow = &attn[(qrow0 + row) * T + kt * 64 + colg];
        *(float4*)&arow[0] = make_float4(acc[0], acc[1], acc[2], acc[3]);
        *(float4*)&arow[4] = make_float4(acc[4], acc[5], acc[6], acc[7]);

        __half2 pv[4];
        pv[0] = __floats2half2_rn(acc[0], acc[1]); pv[1] = __floats2half2_rn(acc[2], acc[3]);
        pv[2] = __floats2half2_rn(acc[4], acc[5]); pv[3] = __floats2half2_rn(acc[6], acc[7]);

        // store this iteration's P and V; ONE barrier; then MMA.
        // (MMA(ki) on buf is protected from the overwrite at ki+2 by sync(ki+1).)
        *(uint4*)&Ps[row * HP + colg] = *(uint4*)pv;
        *(uint4*)&Vs[row * HP + colg] = vreg;
        __syncthreads();

#pragma unroll
        for (int ks = 0; ks < 4; ks++) {
            wmma::fragment<wmma::matrix_a, 16, 16, 16, __half, wmma::row_major> pa;
            wmma::fragment<wmma::matrix_b, 16, 16, 16, __half, wmma::row_major> vb;
            wmma::load_matrix_sync(pa, &Ps[(wq * 16) * HP + ks * 16], HP);
            wmma::load_matrix_sync(vb, &Vs[(ks * 16) * HP + wn * 16], HP);
            wmma::mma_sync(co, pa, vb, co);
        }
    }

    __syncthreads();
    wmma::store_matrix_sync(&Ss[(wq * 16) * HP + wn * 16], co, HP, wmma::mem_row_major);
    __syncthreads();
    float* dst = &g_Opart[(size_t)kc * PSLICE + (qrow0 + row) * HS + colg];
    *(float4*)&dst[0] = *(float4*)&Ss[row * HP + colg];
    *(float4*)&dst[4] = *(float4*)&Ss[row * HP + colg + 4];
}

// ============================================================================
// Launch
// ============================================================================
extern "C" void kernel_launch(void* const* d_in, const int* in_sizes, int n_in,
                              void* d_out, int out_size)
{
    const float* x  = (const float*)d_in[0];
    const float* Wq = (const float*)d_in[1];
    const float* bq = (const float*)d_in[2];
    const float* Wk = (const float*)d_in[3];
    const float* bk = (const float*)d_in[4];
    const float* Wv = (const float*)d_in[5];
    const float* bv = (const float*)d_in[6];
    const float* Wo = (const float*)d_in[7];
    const float* bo = (const float*)d_in[8];

    float* out  = (float*)d_out;
    float* attn = out + OUT_ELEMS;

    __half *xh, *Wpk, *Woh, *QKVp, *Orp;
    float *Op, *bpk;
    cudaGetSymbolAddress((void**)&xh,   g_xh);
    cudaGetSymbolAddress((void**)&Wpk,  g_Wpk);
    cudaGetSymbolAddress((void**)&bpk,  g_bpk);
    cudaGetSymbolAddress((void**)&Woh,  g_Woh);
    cudaGetSymbolAddress((void**)&QKVp, g_QKV);
    cudaGetSymbolAddress((void**)&Op,   g_Opart);
    cudaGetSymbolAddress((void**)&Orp,  g_Ored);

    cudaFuncSetAttribute(gemm_f16_v2, cudaFuncAttributeMaxDynamicSharedMemorySize,
                         GEMM_SMEM);
    cudaFuncSetAttribute(attn_scores, cudaFuncAttributeMaxDynamicSharedMemorySize,
                         ASA_SMEM);
    cudaFuncSetAttribute(attn_combine, cudaFuncAttributeMaxDynamicSharedMemorySize,
                         ACB_SMEM);

    // 1. conversions + weight packing
    conv_pack<<<2048, 256>>>(x, Wq, bq, Wk, bk, Wv, bv, Wo);

    // 2. fused QKV projection: [8192 x 2176] = xh @ Wpk + bpk (fp16 out)
    gemm_f16_v2<<<dim3(QKVP / 128, (B * T) / 128), 256, GEMM_SMEM>>>(
        xh, Wpk, bpk, QKVp, nullptr, B * T, QKVP, HID);

    // 3. stage A: scores -> E + row sums
    attn_scores<<<dim3(QT, NH, B), 512, ASA_SMEM>>>();

    // 4. stage B: head-average -> attn + partial O
    attn_combine<<<dim3(KC, QT, B), 512, ACB_SMEM>>>(attn);

    // 5. reduce partials -> fp16 O
    reduceN_f16<<<(int)((PSLICE / 4 + 255) / 256), 256>>>(Op);

    // 6. out = O @ Wo + bo  (fp16 MMA, fp32 out)
    gemm_f16_v2<<<dim3(HID / 128, (B * T) / 128), 256, GEMM_SMEM>>>(
        Orp, Woh, bo, nullptr, out, B * T, HID, HS);
}